// round 5
// baseline (speedup 1.0000x reference)
#include <cuda_runtime.h>
#include <cstdint>
#include <math.h>

#define NN 100000
#define FI 128
#define H  64

// Scratch (device globals: no allocations allowed). 16B-aligned for float4 access.
__device__ __align__(16) float g_xl[(size_t)NN * H];   // per-node scatter source
__device__ __align__(16) float g_xb[(size_t)NN * H];   // root-path term + bias
__device__ __align__(16) float g_s [(size_t)NN * H];   // scatter accumulator
__device__ __align__(16) float g_cnt[NN];              // in-degree
__device__ __align__(16) float g_hq[(size_t)NN * H];   // h1 @ Wo1
__device__ __align__(16) float g_W2o[H * H];           // We2 @ Wo1
__device__ __align__(16) float g_b2o[H];               // be2 @ Wo1 + bo1

// ---------------------------------------------------------------- prep (tiny)
__global__ void k_prep(const float* __restrict__ We2, const float* __restrict__ Wo1,
                       const float* __restrict__ be2, const float* __restrict__ bo1) {
    int j = threadIdx.x;                  // 0..63
    float accb = bo1[j];
    for (int k = 0; k < H; k++) accb += be2[k] * Wo1[k * H + j];
    g_b2o[j] = accb;
    for (int i = 0; i < H; i++) {
        float acc = 0.f;
        for (int k = 0; k < H; k++) acc += We2[i * H + k] * Wo1[k * H + j];
        g_W2o[i * H + j] = acc;
    }
}

// ------------------------------------------------- node linear 128 -> 64
// mode 0: g_xl = x@W           (also zero g_s, g_cnt)
// mode 1: g_xb = x@W + bias
__global__ void __launch_bounds__(256) k_node_lin128(const float* __restrict__ x,
                                                     const float* __restrict__ W,
                                                     const float* __restrict__ bias,
                                                     int N, int mode) {
    __shared__ float ws[FI * H];          // 32 KB
    __shared__ float xs[16 * FI];         // 8 KB
    int tid = threadIdx.x;
    #pragma unroll
    for (int i = 0; i < (FI * H / 4) / 256; i++)   // 8 iters
        ((float4*)ws)[tid + i * 256] = ((const float4*)W)[tid + i * 256];

    int nsub = tid >> 4, jg = tid & 15, j0 = jg * 4;
    int n = blockIdx.x * 16 + nsub;
    if (n < N) {
        const float4* xg = (const float4*)(x + (size_t)n * FI) + jg * 2;
        float4* xd = (float4*)(xs + nsub * FI) + jg * 2;
        xd[0] = xg[0]; xd[1] = xg[1];
    }
    __syncthreads();
    if (n >= N) return;

    float a0 = 0.f, a1 = 0.f, a2 = 0.f, a3 = 0.f;
    #pragma unroll 8
    for (int i = 0; i < FI; i++) {
        float xv = xs[nsub * FI + i];
        float4 w = *(const float4*)&ws[i * H + j0];
        a0 = fmaf(xv, w.x, a0); a1 = fmaf(xv, w.y, a1);
        a2 = fmaf(xv, w.z, a2); a3 = fmaf(xv, w.w, a3);
    }
    size_t o = (size_t)n * H + j0;
    if (mode == 0) {
        *(float4*)&g_xl[o] = make_float4(a0, a1, a2, a3);
        *(float4*)&g_s[o]  = make_float4(0.f, 0.f, 0.f, 0.f);
        if (jg == 0) g_cnt[n] = 0.f;
    } else {
        float4 b = *(const float4*)&bias[j0];
        *(float4*)&g_xb[o] = make_float4(a0 + b.x, a1 + b.y, a2 + b.z, a3 + b.w);
    }
}

// ------------------------------------------------- edge scatter (g_xl[src] += into g_s[tgt])
__global__ void k_scatter(const int* __restrict__ ei, int E, int do_cnt) {
    unsigned idx = blockIdx.x * 256u + threadIdx.x;
    unsigned e = idx >> 4;
    if (e >= (unsigned)E) return;
    int k4 = (int)(idx & 15u) * 4;
    int s = ei[e];
    int t = ei[(size_t)E + e];
    float4 v = *(const float4*)(g_xl + (size_t)s * H + k4);
    float* p = g_s + (size_t)t * H + k4;
    atomicAdd(p + 0, v.x);
    atomicAdd(p + 1, v.y);
    atomicAdd(p + 2, v.z);
    atomicAdd(p + 3, v.w);
    if (do_cnt && k4 == 0) atomicAdd(g_cnt + t, 1.0f);
}

// ------------------------------------------------- h0 = relu(s/cnt + xb); project with Wl1/Wr1
__global__ void __launch_bounds__(256) k_node_mid(const float* __restrict__ Wl,
                                                  const float* __restrict__ Wr,
                                                  const float* __restrict__ bl, int N) {
    __shared__ float wls[H * H], wrs[H * H], hs[16 * H];   // 36 KB
    int tid = threadIdx.x;
    #pragma unroll
    for (int i = 0; i < (H * H / 4) / 256; i++) {          // 4 iters
        ((float4*)wls)[tid + i * 256] = ((const float4*)Wl)[tid + i * 256];
        ((float4*)wrs)[tid + i * 256] = ((const float4*)Wr)[tid + i * 256];
    }
    int nsub = tid >> 4, j0 = (tid & 15) * 4;
    int n = blockIdx.x * 16 + nsub;
    if (n < N) {
        size_t o = (size_t)n * H + j0;
        float inv = 1.0f / fmaxf(g_cnt[n], 1.0f);
        float4 s4 = *(const float4*)&g_s[o];
        float4 b4 = *(const float4*)&g_xb[o];
        hs[nsub * H + j0 + 0] = fmaxf(fmaf(s4.x, inv, b4.x), 0.f);
        hs[nsub * H + j0 + 1] = fmaxf(fmaf(s4.y, inv, b4.y), 0.f);
        hs[nsub * H + j0 + 2] = fmaxf(fmaf(s4.z, inv, b4.z), 0.f);
        hs[nsub * H + j0 + 3] = fmaxf(fmaf(s4.w, inv, b4.w), 0.f);
        *(float4*)&g_s[o] = make_float4(0.f, 0.f, 0.f, 0.f);   // reset for layer-2 scatter
    }
    __syncthreads();
    if (n >= N) return;

    float a0 = 0, a1 = 0, a2 = 0, a3 = 0, c0 = 0, c1 = 0, c2 = 0, c3 = 0;
    #pragma unroll 8
    for (int k = 0; k < H; k++) {
        float hv = hs[nsub * H + k];
        float4 wl4 = *(const float4*)&wls[k * H + j0];
        float4 wr4 = *(const float4*)&wrs[k * H + j0];
        a0 = fmaf(hv, wl4.x, a0); a1 = fmaf(hv, wl4.y, a1);
        a2 = fmaf(hv, wl4.z, a2); a3 = fmaf(hv, wl4.w, a3);
        c0 = fmaf(hv, wr4.x, c0); c1 = fmaf(hv, wr4.y, c1);
        c2 = fmaf(hv, wr4.z, c2); c3 = fmaf(hv, wr4.w, c3);
    }
    size_t o = (size_t)n * H + j0;
    float4 b = *(const float4*)&bl[j0];
    *(float4*)&g_xl[o] = make_float4(a0, a1, a2, a3);
    *(float4*)&g_xb[o] = make_float4(c0 + b.x, c1 + b.y, c2 + b.z, c3 + b.w);
}

// ------------------------------------------------- h1 = relu(s/cnt + xb); g_hq = h1 @ Wo1
__global__ void __launch_bounds__(256) k_node_fin(const float* __restrict__ Wo1, int N) {
    __shared__ float ws[H * H], hs[16 * H];   // 20 KB
    int tid = threadIdx.x;
    #pragma unroll
    for (int i = 0; i < (H * H / 4) / 256; i++)
        ((float4*)ws)[tid + i * 256] = ((const float4*)Wo1)[tid + i * 256];
    int nsub = tid >> 4, j0 = (tid & 15) * 4;
    int n = blockIdx.x * 16 + nsub;
    if (n < N) {
        size_t o = (size_t)n * H + j0;
        float inv = 1.0f / fmaxf(g_cnt[n], 1.0f);
        float4 s4 = *(const float4*)&g_s[o];
        float4 b4 = *(const float4*)&g_xb[o];
        hs[nsub * H + j0 + 0] = fmaxf(fmaf(s4.x, inv, b4.x), 0.f);
        hs[nsub * H + j0 + 1] = fmaxf(fmaf(s4.y, inv, b4.y), 0.f);
        hs[nsub * H + j0 + 2] = fmaxf(fmaf(s4.z, inv, b4.z), 0.f);
        hs[nsub * H + j0 + 3] = fmaxf(fmaf(s4.w, inv, b4.w), 0.f);
    }
    __syncthreads();
    if (n >= N) return;

    float a0 = 0, a1 = 0, a2 = 0, a3 = 0;
    #pragma unroll 8
    for (int k = 0; k < H; k++) {
        float hv = hs[nsub * H + k];
        float4 w4 = *(const float4*)&ws[k * H + j0];
        a0 = fmaf(hv, w4.x, a0); a1 = fmaf(hv, w4.y, a1);
        a2 = fmaf(hv, w4.z, a2); a3 = fmaf(hv, w4.w, a3);
    }
    *(float4*)&g_hq[(size_t)n * H + j0] = make_float4(a0, a1, a2, a3);
}

// ------------------------------------------------- per-edge head (thread per edge)
__global__ void __launch_bounds__(128) k_edge(const int* __restrict__ ei, int E,
                                              const float* __restrict__ edge_attr,
                                              const float* __restrict__ We1,
                                              const float* __restrict__ be1,
                                              const float* __restrict__ Wo2,
                                              const float* __restrict__ bo2,
                                              float* __restrict__ out) {
    __shared__ float we1t[H * 16];   // [k][i] transposed
    __shared__ float w2os[H * H];
    __shared__ float be1s[H], b2os[H], wo2s[H];
    __shared__ float bo2s;
    int tid = threadIdx.x;
    for (int idx = tid; idx < H * 16; idx += 128) {
        int kk = idx >> 4, ii = idx & 15;
        we1t[idx] = We1[ii * H + kk];
    }
    for (int idx = tid; idx < H * H; idx += 128) w2os[idx] = g_W2o[idx];
    if (tid < H) { be1s[tid] = be1[tid]; b2os[tid] = g_b2o[tid]; wo2s[tid] = Wo2[tid]; }
    if (tid == 0) bo2s = bo2[0];
    __syncthreads();

    long long e = (long long)blockIdx.x * 128 + tid;
    if (e >= E) return;
    int s = ei[e];
    int t = ei[(size_t)E + e];

    float ea[16];
    const float4* eap = (const float4*)(edge_attr + (size_t)e * 16);
    #pragma unroll
    for (int c = 0; c < 4; c++) {
        float4 v = eap[c];
        ea[c * 4 + 0] = v.x; ea[c * 4 + 1] = v.y; ea[c * 4 + 2] = v.z; ea[c * 4 + 3] = v.w;
    }

    float acc[H];
    const float4* hqs = (const float4*)(g_hq + (size_t)s * H);
    const float4* hqt = (const float4*)(g_hq + (size_t)t * H);
    #pragma unroll
    for (int q = 0; q < 16; q++) {
        float4 a = hqs[q], b = hqt[q], c = *(const float4*)&b2os[q * 4];
        acc[q * 4 + 0] = a.x + b.x + c.x;
        acc[q * 4 + 1] = a.y + b.y + c.y;
        acc[q * 4 + 2] = a.z + b.z + c.z;
        acc[q * 4 + 3] = a.w + b.w + c.w;
    }

    for (int k = 0; k < H; k++) {
        float z = be1s[k];
        #pragma unroll
        for (int q = 0; q < 4; q++) {
            float4 w = *(const float4*)&we1t[k * 16 + q * 4];
            z = fmaf(ea[q * 4 + 0], w.x, z);
            z = fmaf(ea[q * 4 + 1], w.y, z);
            z = fmaf(ea[q * 4 + 2], w.z, z);
            z = fmaf(ea[q * 4 + 3], w.w, z);
        }
        float r = fmaxf(z, 0.f);
        const float4* wrow = (const float4*)&w2os[k * H];
        #pragma unroll
        for (int q = 0; q < 16; q++) {
            float4 w = wrow[q];
            acc[q * 4 + 0] = fmaf(r, w.x, acc[q * 4 + 0]);
            acc[q * 4 + 1] = fmaf(r, w.y, acc[q * 4 + 1]);
            acc[q * 4 + 2] = fmaf(r, w.z, acc[q * 4 + 2]);
            acc[q * 4 + 3] = fmaf(r, w.w, acc[q * 4 + 3]);
        }
    }

    float o = bo2s;
    #pragma unroll
    for (int q = 0; q < 16; q++) {
        float4 w = *(const float4*)&wo2s[q * 4];
        o = fmaf(fmaxf(acc[q * 4 + 0], 0.f), w.x, o);
        o = fmaf(fmaxf(acc[q * 4 + 1], 0.f), w.y, o);
        o = fmaf(fmaxf(acc[q * 4 + 2], 0.f), w.z, o);
        o = fmaf(fmaxf(acc[q * 4 + 3], 0.f), w.w, o);
    }
    out[e] = 1.0f / (1.0f + expf(-o));
}

// ----------------------------------------------------------------------------
extern "C" void kernel_launch(void* const* d_in, const int* in_sizes, int n_in,
                              void* d_out, int out_size) {
    const float* x   = (const float*)d_in[0];
    const int*   ei  = (const int*)d_in[1];       // int32! (JAX x64 disabled)
    const float* eat = (const float*)d_in[2];
    const float* We1 = (const float*)d_in[3];
    const float* be1 = (const float*)d_in[4];
    const float* We2 = (const float*)d_in[5];
    const float* be2 = (const float*)d_in[6];
    const float* Wl0 = (const float*)d_in[7];
    const float* bl0 = (const float*)d_in[8];
    const float* Wr0 = (const float*)d_in[9];
    const float* Wl1 = (const float*)d_in[10];
    const float* bl1 = (const float*)d_in[11];
    const float* Wr1 = (const float*)d_in[12];
    const float* Wo1 = (const float*)d_in[13];
    const float* bo1 = (const float*)d_in[14];
    const float* Wo2 = (const float*)d_in[15];
    const float* bo2 = (const float*)d_in[16];

    int N = in_sizes[0] / FI;          // 100000
    if (N > NN) N = NN;
    int E = in_sizes[1] / 2;           // 1000000
    float* out = (float*)d_out;

    int nb = (N + 15) / 16;
    unsigned sth = (unsigned)E * 16u;
    unsigned sblocks = (sth + 255u) / 256u;

    k_prep<<<1, H>>>(We2, Wo1, be2, bo1);
    k_node_lin128<<<nb, 256>>>(x, Wl0, nullptr, N, 0);   // g_xl; zero g_s/g_cnt
    k_node_lin128<<<nb, 256>>>(x, Wr0, bl0, N, 1);       // g_xb
    k_scatter<<<sblocks, 256>>>(ei, E, 1);               // layer-0 aggregation + counts
    k_node_mid<<<nb, 256>>>(Wl1, Wr1, bl1, N);           // h0 -> layer-1 projections
    k_scatter<<<sblocks, 256>>>(ei, E, 0);               // layer-1 aggregation
    k_node_fin<<<nb, 256>>>(Wo1, N);                     // h1 -> g_hq
    k_edge<<<(E + 127) / 128, 128>>>(ei, E, eat, We1, be1, Wo2, bo2, out);
}

// round 6
// speedup vs baseline: 1.1445x; 1.1445x over previous
#include <cuda_runtime.h>
#include <cstdint>
#include <math.h>

#define NN 100000
#define FI 128
#define H  64

typedef unsigned long long u64;

__device__ __forceinline__ u64 ffma2(u64 a, u64 b, u64 c) {
    u64 d;
    asm("fma.rn.f32x2 %0, %1, %2, %3;" : "=l"(d) : "l"(a), "l"(b), "l"(c));
    return d;
}
__device__ __forceinline__ u64 fadd2(u64 a, u64 b) {
    u64 d;
    asm("add.rn.f32x2 %0, %1, %2;" : "=l"(d) : "l"(a), "l"(b));
    return d;
}
__device__ __forceinline__ float2 unpack2(u64 p) {
    float2 f;
    asm("mov.b64 {%0,%1}, %2;" : "=f"(f.x), "=f"(f.y) : "l"(p));
    return f;
}
__device__ __forceinline__ u64 pack2(float lo, float hi) {
    u64 p;
    asm("mov.b64 %0, {%1,%2};" : "=l"(p) : "f"(lo), "f"(hi));
    return p;
}

// Scratch (device globals: no allocations allowed). 16B-aligned for float4 access.
__device__ __align__(16) float g_xl[(size_t)NN * H];   // per-node scatter source
__device__ __align__(16) float g_xb[(size_t)NN * H];   // root-path term + bias
__device__ __align__(16) float g_s [(size_t)NN * H];   // scatter accumulator
__device__ __align__(16) float g_cnt[NN];              // in-degree
__device__ __align__(16) float g_hq[(size_t)NN * H];   // h1 @ Wo1
__device__ __align__(16) float g_W2o[H * H];           // We2 @ Wo1
__device__ __align__(16) float g_b2o[H];               // be2 @ Wo1 + bo1

// ---------------------------------------------------------------- prep (tiny)
__global__ void k_prep(const float* __restrict__ We2, const float* __restrict__ Wo1,
                       const float* __restrict__ be2, const float* __restrict__ bo1) {
    int j = threadIdx.x;                  // 0..63
    float accb = bo1[j];
    for (int k = 0; k < H; k++) accb += be2[k] * Wo1[k * H + j];
    g_b2o[j] = accb;
    for (int i = 0; i < H; i++) {
        float acc = 0.f;
        for (int k = 0; k < H; k++) acc += We2[i * H + k] * Wo1[k * H + j];
        g_W2o[i * H + j] = acc;
    }
}

// ------------------------------------------------- node linear 128 -> 64
// mode 0: g_xl = x@W           (also zero g_s, g_cnt)
// mode 1: g_xb = x@W + bias
__global__ void __launch_bounds__(256) k_node_lin128(const float* __restrict__ x,
                                                     const float* __restrict__ W,
                                                     const float* __restrict__ bias,
                                                     int N, int mode) {
    __shared__ float ws[FI * H];          // 32 KB
    __shared__ float xs[16 * FI];         // 8 KB
    int tid = threadIdx.x;
    #pragma unroll
    for (int i = 0; i < (FI * H / 4) / 256; i++)   // 8 iters
        ((float4*)ws)[tid + i * 256] = ((const float4*)W)[tid + i * 256];

    int nsub = tid >> 4, jg = tid & 15, j0 = jg * 4;
    int n = blockIdx.x * 16 + nsub;
    if (n < N) {
        const float4* xg = (const float4*)(x + (size_t)n * FI) + jg * 2;
        float4* xd = (float4*)(xs + nsub * FI) + jg * 2;
        xd[0] = xg[0]; xd[1] = xg[1];
    }
    __syncthreads();
    if (n >= N) return;

    float a0 = 0.f, a1 = 0.f, a2 = 0.f, a3 = 0.f;
    #pragma unroll 8
    for (int i = 0; i < FI; i++) {
        float xv = xs[nsub * FI + i];
        float4 w = *(const float4*)&ws[i * H + j0];
        a0 = fmaf(xv, w.x, a0); a1 = fmaf(xv, w.y, a1);
        a2 = fmaf(xv, w.z, a2); a3 = fmaf(xv, w.w, a3);
    }
    size_t o = (size_t)n * H + j0;
    if (mode == 0) {
        *(float4*)&g_xl[o] = make_float4(a0, a1, a2, a3);
        *(float4*)&g_s[o]  = make_float4(0.f, 0.f, 0.f, 0.f);
        if (jg == 0) g_cnt[n] = 0.f;
    } else {
        float4 b = *(const float4*)&bias[j0];
        *(float4*)&g_xb[o] = make_float4(a0 + b.x, a1 + b.y, a2 + b.z, a3 + b.w);
    }
}

// ------------------------------------------------- edge scatter (g_xl[src] += into g_s[tgt])
__global__ void k_scatter(const int* __restrict__ ei, int E, int do_cnt) {
    unsigned idx = blockIdx.x * 256u + threadIdx.x;
    unsigned e = idx >> 4;
    if (e >= (unsigned)E) return;
    int k4 = (int)(idx & 15u) * 4;
    int s = ei[e];
    int t = ei[(size_t)E + e];
    float4 v = *(const float4*)(g_xl + (size_t)s * H + k4);
    float* p = g_s + (size_t)t * H + k4;
    asm volatile("red.global.add.v4.f32 [%0], {%1,%2,%3,%4};"
                 :: "l"(p), "f"(v.x), "f"(v.y), "f"(v.z), "f"(v.w) : "memory");
    if (do_cnt && k4 == 0) atomicAdd(g_cnt + t, 1.0f);
}

// ------------------------------------------------- h0 = relu(s/cnt + xb); project with Wl1/Wr1
__global__ void __launch_bounds__(256) k_node_mid(const float* __restrict__ Wl,
                                                  const float* __restrict__ Wr,
                                                  const float* __restrict__ bl, int N) {
    __shared__ float wls[H * H], wrs[H * H], hs[16 * H];   // 36 KB
    int tid = threadIdx.x;
    #pragma unroll
    for (int i = 0; i < (H * H / 4) / 256; i++) {          // 4 iters
        ((float4*)wls)[tid + i * 256] = ((const float4*)Wl)[tid + i * 256];
        ((float4*)wrs)[tid + i * 256] = ((const float4*)Wr)[tid + i * 256];
    }
    int nsub = tid >> 4, j0 = (tid & 15) * 4;
    int n = blockIdx.x * 16 + nsub;
    if (n < N) {
        size_t o = (size_t)n * H + j0;
        float inv = 1.0f / fmaxf(g_cnt[n], 1.0f);
        float4 s4 = *(const float4*)&g_s[o];
        float4 b4 = *(const float4*)&g_xb[o];
        hs[nsub * H + j0 + 0] = fmaxf(fmaf(s4.x, inv, b4.x), 0.f);
        hs[nsub * H + j0 + 1] = fmaxf(fmaf(s4.y, inv, b4.y), 0.f);
        hs[nsub * H + j0 + 2] = fmaxf(fmaf(s4.z, inv, b4.z), 0.f);
        hs[nsub * H + j0 + 3] = fmaxf(fmaf(s4.w, inv, b4.w), 0.f);
        *(float4*)&g_s[o] = make_float4(0.f, 0.f, 0.f, 0.f);   // reset for layer-2 scatter
    }
    __syncthreads();
    if (n >= N) return;

    float a0 = 0, a1 = 0, a2 = 0, a3 = 0, c0 = 0, c1 = 0, c2 = 0, c3 = 0;
    #pragma unroll 8
    for (int k = 0; k < H; k++) {
        float hv = hs[nsub * H + k];
        float4 wl4 = *(const float4*)&wls[k * H + j0];
        float4 wr4 = *(const float4*)&wrs[k * H + j0];
        a0 = fmaf(hv, wl4.x, a0); a1 = fmaf(hv, wl4.y, a1);
        a2 = fmaf(hv, wl4.z, a2); a3 = fmaf(hv, wl4.w, a3);
        c0 = fmaf(hv, wr4.x, c0); c1 = fmaf(hv, wr4.y, c1);
        c2 = fmaf(hv, wr4.z, c2); c3 = fmaf(hv, wr4.w, c3);
    }
    size_t o = (size_t)n * H + j0;
    float4 b = *(const float4*)&bl[j0];
    *(float4*)&g_xl[o] = make_float4(a0, a1, a2, a3);
    *(float4*)&g_xb[o] = make_float4(c0 + b.x, c1 + b.y, c2 + b.z, c3 + b.w);
}

// ------------------------------------------------- h1 = relu(s/cnt + xb); g_hq = h1 @ Wo1
__global__ void __launch_bounds__(256) k_node_fin(const float* __restrict__ Wo1, int N) {
    __shared__ float ws[H * H], hs[16 * H];   // 20 KB
    int tid = threadIdx.x;
    #pragma unroll
    for (int i = 0; i < (H * H / 4) / 256; i++)
        ((float4*)ws)[tid + i * 256] = ((const float4*)Wo1)[tid + i * 256];
    int nsub = tid >> 4, j0 = (tid & 15) * 4;
    int n = blockIdx.x * 16 + nsub;
    if (n < N) {
        size_t o = (size_t)n * H + j0;
        float inv = 1.0f / fmaxf(g_cnt[n], 1.0f);
        float4 s4 = *(const float4*)&g_s[o];
        float4 b4 = *(const float4*)&g_xb[o];
        hs[nsub * H + j0 + 0] = fmaxf(fmaf(s4.x, inv, b4.x), 0.f);
        hs[nsub * H + j0 + 1] = fmaxf(fmaf(s4.y, inv, b4.y), 0.f);
        hs[nsub * H + j0 + 2] = fmaxf(fmaf(s4.z, inv, b4.z), 0.f);
        hs[nsub * H + j0 + 3] = fmaxf(fmaf(s4.w, inv, b4.w), 0.f);
    }
    __syncthreads();
    if (n >= N) return;

    float a0 = 0, a1 = 0, a2 = 0, a3 = 0;
    #pragma unroll 8
    for (int k = 0; k < H; k++) {
        float hv = hs[nsub * H + k];
        float4 w4 = *(const float4*)&ws[k * H + j0];
        a0 = fmaf(hv, w4.x, a0); a1 = fmaf(hv, w4.y, a1);
        a2 = fmaf(hv, w4.z, a2); a3 = fmaf(hv, w4.w, a3);
    }
    *(float4*)&g_hq[(size_t)n * H + j0] = make_float4(a0, a1, a2, a3);
}

// ------------------------------------------------- per-edge head (thread per edge, f32x2 packed)
__global__ void __launch_bounds__(128) k_edge(const int* __restrict__ ei, int E,
                                              const float* __restrict__ edge_attr,
                                              const float* __restrict__ We1,
                                              const float* __restrict__ be1,
                                              const float* __restrict__ Wo2,
                                              const float* __restrict__ bo2,
                                              float* __restrict__ out) {
    __shared__ float we1t[H * 16];   // [k][i] transposed
    __shared__ float w2os[H * H];
    __shared__ float be1s[H], b2os[H], wo2s[H];
    __shared__ float bo2s;
    int tid = threadIdx.x;
    for (int idx = tid; idx < H * 16; idx += 128) {
        int kk = idx >> 4, ii = idx & 15;
        we1t[idx] = We1[ii * H + kk];
    }
    for (int idx = tid; idx < H * H; idx += 128) w2os[idx] = g_W2o[idx];
    if (tid < H) { be1s[tid] = be1[tid]; b2os[tid] = g_b2o[tid]; wo2s[tid] = Wo2[tid]; }
    if (tid == 0) bo2s = bo2[0];
    __syncthreads();

    long long e = (long long)blockIdx.x * 128 + tid;
    if (e >= E) return;
    int s = ei[e];
    int t = ei[(size_t)E + e];

    // edge_attr as 8 packed f32x2
    u64 ea2[8];
    const float4* eap = (const float4*)(edge_attr + (size_t)e * 16);
    #pragma unroll
    for (int c = 0; c < 4; c++) {
        float4 v = eap[c];
        ea2[2 * c + 0] = pack2(v.x, v.y);
        ea2[2 * c + 1] = pack2(v.z, v.w);
    }

    // acc = hq[s] + hq[t] + b2o  (packed pairs)
    u64 acc2[32];
    const u64* hqs  = (const u64*)(g_hq + (size_t)s * H);
    const u64* hqt  = (const u64*)(g_hq + (size_t)t * H);
    const u64* b2o2 = (const u64*)b2os;
    #pragma unroll
    for (int q = 0; q < 32; q++)
        acc2[q] = fadd2(fadd2(hqs[q], hqt[q]), b2o2[q]);

    #pragma unroll 2
    for (int k = 0; k < H; k++) {
        u64 z2 = pack2(be1s[k], 0.0f);
        const u64* wrow = (const u64*)&we1t[k * 16];
        #pragma unroll
        for (int q = 0; q < 8; q++) z2 = ffma2(ea2[q], wrow[q], z2);
        float2 zz = unpack2(z2);
        float r = fmaxf(zz.x + zz.y, 0.f);
        u64 rr = pack2(r, r);
        const u64* w2row = (const u64*)&w2os[k * H];
        #pragma unroll
        for (int q = 0; q < 32; q++) acc2[q] = ffma2(rr, w2row[q], acc2[q]);
    }

    float o = bo2s;
    #pragma unroll
    for (int q = 0; q < 32; q++) {
        float2 a = unpack2(acc2[q]);
        o = fmaf(fmaxf(a.x, 0.f), wo2s[2 * q + 0], o);
        o = fmaf(fmaxf(a.y, 0.f), wo2s[2 * q + 1], o);
    }
    out[e] = 1.0f / (1.0f + expf(-o));
}

// ----------------------------------------------------------------------------
extern "C" void kernel_launch(void* const* d_in, const int* in_sizes, int n_in,
                              void* d_out, int out_size) {
    const float* x   = (const float*)d_in[0];
    const int*   ei  = (const int*)d_in[1];       // int32 (JAX x64 disabled)
    const float* eat = (const float*)d_in[2];
    const float* We1 = (const float*)d_in[3];
    const float* be1 = (const float*)d_in[4];
    const float* We2 = (const float*)d_in[5];
    const float* be2 = (const float*)d_in[6];
    const float* Wl0 = (const float*)d_in[7];
    const float* bl0 = (const float*)d_in[8];
    const float* Wr0 = (const float*)d_in[9];
    const float* Wl1 = (const float*)d_in[10];
    const float* bl1 = (const float*)d_in[11];
    const float* Wr1 = (const float*)d_in[12];
    const float* Wo1 = (const float*)d_in[13];
    const float* bo1 = (const float*)d_in[14];
    const float* Wo2 = (const float*)d_in[15];
    const float* bo2 = (const float*)d_in[16];

    int N = in_sizes[0] / FI;          // 100000
    if (N > NN) N = NN;
    int E = in_sizes[1] / 2;           // 1000000
    float* out = (float*)d_out;

    int nb = (N + 15) / 16;
    unsigned sth = (unsigned)E * 16u;
    unsigned sblocks = (sth + 255u) / 256u;

    k_prep<<<1, H>>>(We2, Wo1, be2, bo1);
    k_node_lin128<<<nb, 256>>>(x, Wl0, nullptr, N, 0);   // g_xl; zero g_s/g_cnt
    k_node_lin128<<<nb, 256>>>(x, Wr0, bl0, N, 1);       // g_xb
    k_scatter<<<sblocks, 256>>>(ei, E, 1);               // layer-0 aggregation + counts
    k_node_mid<<<nb, 256>>>(Wl1, Wr1, bl1, N);           // h0 -> layer-1 projections
    k_scatter<<<sblocks, 256>>>(ei, E, 0);               // layer-1 aggregation
    k_node_fin<<<nb, 256>>>(Wo1, N);                     // h1 -> g_hq
    k_edge<<<(E + 127) / 128, 128>>>(ei, E, eat, We1, be1, Wo2, bo2, out);
}

// round 7
// speedup vs baseline: 1.2232x; 1.0687x over previous
#include <cuda_runtime.h>
#include <cstdint>
#include <math.h>

#define NN 100000
#define FI 128
#define H  64
#define TE 128   // edges per block in k_edge

typedef unsigned long long u64;

__device__ __forceinline__ u64 ffma2(u64 a, u64 b, u64 c) {
    u64 d;
    asm("fma.rn.f32x2 %0, %1, %2, %3;" : "=l"(d) : "l"(a), "l"(b), "l"(c));
    return d;
}
__device__ __forceinline__ float2 unpack2(u64 p) {
    float2 f;
    asm("mov.b64 {%0,%1}, %2;" : "=f"(f.x), "=f"(f.y) : "l"(p));
    return f;
}
__device__ __forceinline__ u64 pack2(float lo, float hi) {
    u64 p;
    asm("mov.b64 %0, {%1,%2};" : "=l"(p) : "f"(lo), "f"(hi));
    return p;
}

// Scratch (device globals: no allocations allowed). 16B-aligned for float4 access.
__device__ __align__(16) float g_xl[(size_t)NN * H];   // per-node scatter source
__device__ __align__(16) float g_xb[(size_t)NN * H];   // root-path term + bias
__device__ __align__(16) float g_s [(size_t)NN * H];   // scatter accumulator
__device__ __align__(16) float g_cnt[NN];              // in-degree
__device__ __align__(16) float g_hq[(size_t)NN * H];   // h1 @ Wo1
__device__ __align__(16) float g_W2o[H * H];           // We2 @ Wo1
__device__ __align__(16) float g_b2o[H];               // be2 @ Wo1 + bo1

// ---------------------------------------------------------------- prep (tiny)
__global__ void k_prep(const float* __restrict__ We2, const float* __restrict__ Wo1,
                       const float* __restrict__ be2, const float* __restrict__ bo1) {
    int j = threadIdx.x;                  // 0..63
    float accb = bo1[j];
    for (int k = 0; k < H; k++) accb += be2[k] * Wo1[k * H + j];
    g_b2o[j] = accb;
    for (int i = 0; i < H; i++) {
        float acc = 0.f;
        for (int k = 0; k < H; k++) acc += We2[i * H + k] * Wo1[k * H + j];
        g_W2o[i * H + j] = acc;
    }
}

// ------------------------------------------------- node linear 128 -> 64
__global__ void __launch_bounds__(256) k_node_lin128(const float* __restrict__ x,
                                                     const float* __restrict__ W,
                                                     const float* __restrict__ bias,
                                                     int N, int mode) {
    __shared__ float ws[FI * H];          // 32 KB
    __shared__ float xs[16 * FI];         // 8 KB
    int tid = threadIdx.x;
    #pragma unroll
    for (int i = 0; i < (FI * H / 4) / 256; i++)
        ((float4*)ws)[tid + i * 256] = ((const float4*)W)[tid + i * 256];

    int nsub = tid >> 4, jg = tid & 15, j0 = jg * 4;
    int n = blockIdx.x * 16 + nsub;
    if (n < N) {
        const float4* xg = (const float4*)(x + (size_t)n * FI) + jg * 2;
        float4* xd = (float4*)(xs + nsub * FI) + jg * 2;
        xd[0] = xg[0]; xd[1] = xg[1];
    }
    __syncthreads();
    if (n >= N) return;

    float a0 = 0.f, a1 = 0.f, a2 = 0.f, a3 = 0.f;
    #pragma unroll 8
    for (int i = 0; i < FI; i++) {
        float xv = xs[nsub * FI + i];
        float4 w = *(const float4*)&ws[i * H + j0];
        a0 = fmaf(xv, w.x, a0); a1 = fmaf(xv, w.y, a1);
        a2 = fmaf(xv, w.z, a2); a3 = fmaf(xv, w.w, a3);
    }
    size_t o = (size_t)n * H + j0;
    if (mode == 0) {
        *(float4*)&g_xl[o] = make_float4(a0, a1, a2, a3);
        *(float4*)&g_s[o]  = make_float4(0.f, 0.f, 0.f, 0.f);
        if (jg == 0) g_cnt[n] = 0.f;
    } else {
        float4 b = *(const float4*)&bias[j0];
        *(float4*)&g_xb[o] = make_float4(a0 + b.x, a1 + b.y, a2 + b.z, a3 + b.w);
    }
}

// ------------------------------------------------- edge scatter
__global__ void k_scatter(const int* __restrict__ ei, int E, int do_cnt) {
    unsigned idx = blockIdx.x * 256u + threadIdx.x;
    unsigned e = idx >> 4;
    if (e >= (unsigned)E) return;
    int k4 = (int)(idx & 15u) * 4;
    int s = ei[e];
    int t = ei[(size_t)E + e];
    float4 v = *(const float4*)(g_xl + (size_t)s * H + k4);
    float* p = g_s + (size_t)t * H + k4;
    asm volatile("red.global.add.v4.f32 [%0], {%1,%2,%3,%4};"
                 :: "l"(p), "f"(v.x), "f"(v.y), "f"(v.z), "f"(v.w) : "memory");
    if (do_cnt && k4 == 0) atomicAdd(g_cnt + t, 1.0f);
}

// ------------------------------------------------- h0 = relu(s/cnt + xb); project Wl1/Wr1
__global__ void __launch_bounds__(256) k_node_mid(const float* __restrict__ Wl,
                                                  const float* __restrict__ Wr,
                                                  const float* __restrict__ bl, int N) {
    __shared__ float wls[H * H], wrs[H * H], hs[16 * H];
    int tid = threadIdx.x;
    #pragma unroll
    for (int i = 0; i < (H * H / 4) / 256; i++) {
        ((float4*)wls)[tid + i * 256] = ((const float4*)Wl)[tid + i * 256];
        ((float4*)wrs)[tid + i * 256] = ((const float4*)Wr)[tid + i * 256];
    }
    int nsub = tid >> 4, j0 = (tid & 15) * 4;
    int n = blockIdx.x * 16 + nsub;
    if (n < N) {
        size_t o = (size_t)n * H + j0;
        float inv = 1.0f / fmaxf(g_cnt[n], 1.0f);
        float4 s4 = *(const float4*)&g_s[o];
        float4 b4 = *(const float4*)&g_xb[o];
        hs[nsub * H + j0 + 0] = fmaxf(fmaf(s4.x, inv, b4.x), 0.f);
        hs[nsub * H + j0 + 1] = fmaxf(fmaf(s4.y, inv, b4.y), 0.f);
        hs[nsub * H + j0 + 2] = fmaxf(fmaf(s4.z, inv, b4.z), 0.f);
        hs[nsub * H + j0 + 3] = fmaxf(fmaf(s4.w, inv, b4.w), 0.f);
        *(float4*)&g_s[o] = make_float4(0.f, 0.f, 0.f, 0.f);
    }
    __syncthreads();
    if (n >= N) return;

    float a0 = 0, a1 = 0, a2 = 0, a3 = 0, c0 = 0, c1 = 0, c2 = 0, c3 = 0;
    #pragma unroll 8
    for (int k = 0; k < H; k++) {
        float hv = hs[nsub * H + k];
        float4 wl4 = *(const float4*)&wls[k * H + j0];
        float4 wr4 = *(const float4*)&wrs[k * H + j0];
        a0 = fmaf(hv, wl4.x, a0); a1 = fmaf(hv, wl4.y, a1);
        a2 = fmaf(hv, wl4.z, a2); a3 = fmaf(hv, wl4.w, a3);
        c0 = fmaf(hv, wr4.x, c0); c1 = fmaf(hv, wr4.y, c1);
        c2 = fmaf(hv, wr4.z, c2); c3 = fmaf(hv, wr4.w, c3);
    }
    size_t o = (size_t)n * H + j0;
    float4 b = *(const float4*)&bl[j0];
    *(float4*)&g_xl[o] = make_float4(a0, a1, a2, a3);
    *(float4*)&g_xb[o] = make_float4(c0 + b.x, c1 + b.y, c2 + b.z, c3 + b.w);
}

// ------------------------------------------------- h1 = relu(s/cnt + xb); g_hq = h1 @ Wo1
__global__ void __launch_bounds__(256) k_node_fin(const float* __restrict__ Wo1, int N) {
    __shared__ float ws[H * H], hs[16 * H];
    int tid = threadIdx.x;
    #pragma unroll
    for (int i = 0; i < (H * H / 4) / 256; i++)
        ((float4*)ws)[tid + i * 256] = ((const float4*)Wo1)[tid + i * 256];
    int nsub = tid >> 4, j0 = (tid & 15) * 4;
    int n = blockIdx.x * 16 + nsub;
    if (n < N) {
        size_t o = (size_t)n * H + j0;
        float inv = 1.0f / fmaxf(g_cnt[n], 1.0f);
        float4 s4 = *(const float4*)&g_s[o];
        float4 b4 = *(const float4*)&g_xb[o];
        hs[nsub * H + j0 + 0] = fmaxf(fmaf(s4.x, inv, b4.x), 0.f);
        hs[nsub * H + j0 + 1] = fmaxf(fmaf(s4.y, inv, b4.y), 0.f);
        hs[nsub * H + j0 + 2] = fmaxf(fmaf(s4.z, inv, b4.z), 0.f);
        hs[nsub * H + j0 + 3] = fmaxf(fmaf(s4.w, inv, b4.w), 0.f);
    }
    __syncthreads();
    if (n >= N) return;

    float a0 = 0, a1 = 0, a2 = 0, a3 = 0;
    #pragma unroll 8
    for (int k = 0; k < H; k++) {
        float hv = hs[nsub * H + k];
        float4 w4 = *(const float4*)&ws[k * H + j0];
        a0 = fmaf(hv, w4.x, a0); a1 = fmaf(hv, w4.y, a1);
        a2 = fmaf(hv, w4.z, a2); a3 = fmaf(hv, w4.w, a3);
    }
    *(float4*)&g_hq[(size_t)n * H + j0] = make_float4(a0, a1, a2, a3);
}

// ------------------------------------------------- per-edge head: block-tiled GEMM
// 128 edges/block, 256 threads. Phase A: z[k][e]=relu(ea.We1+be1) into smem.
// Phase B: thread owns 4 edges x 8 j; 3 LDS feed 16 ffma2 per k-step.
struct __align__(16) EdgeSmem {
    float zs[H][TE];        // 32 KB  (k-major)
    float w2os[H][H];       // 16 KB
    float we1t[H][16];      // 4 KB   ([k][i])
    float be1s[H];
    float b2os[H];
    float wo2s[H];
    int   sidx[TE];
    int   tidx[TE];
    float bo2s;
};

__global__ void __launch_bounds__(256) k_edge(const int* __restrict__ ei, int E,
                                              const float* __restrict__ edge_attr,
                                              const float* __restrict__ We1,
                                              const float* __restrict__ be1,
                                              const float* __restrict__ Wo2,
                                              const float* __restrict__ bo2,
                                              float* __restrict__ out) {
    extern __shared__ char smem_raw[];
    EdgeSmem* S = (EdgeSmem*)smem_raw;
    int tid = threadIdx.x;
    long long e_base = (long long)blockIdx.x * TE;

    // ---- cooperative smem fill
    #pragma unroll
    for (int i = 0; i < (H * H / 4) / 256; i++)
        ((float4*)S->w2os)[tid + i * 256] = ((const float4*)g_W2o)[tid + i * 256];
    #pragma unroll
    for (int r = 0; r < 4; r++) {
        int idx = tid + r * 256;             // 0..1023
        int kk = idx >> 4, ii = idx & 15;
        S->we1t[kk][ii] = We1[ii * H + kk];
    }
    if (tid < H) {
        S->be1s[tid] = be1[tid];
        S->b2os[tid] = g_b2o[tid];
        S->wo2s[tid] = Wo2[tid];
    }
    if (tid == 0) S->bo2s = bo2[0];
    if (tid < TE) {
        long long e = e_base + tid;
        S->sidx[tid] = (e < E) ? ei[e] : 0;
    } else {
        int el = tid - TE;
        long long e = e_base + el;
        S->tidx[el] = (e < E) ? ei[(size_t)E + e] : 0;
    }
    __syncthreads();

    // ---- Phase A: zs[k][e] = relu(ea . We1[:,k] + be1[k]); 2 threads per edge
    {
        int th = tid >> 7;            // 0/1 -> k half
        int el = tid & (TE - 1);
        long long e = e_base + el;
        float ea[16];
        if (e < E) {
            const float4* eap = (const float4*)(edge_attr + (size_t)e * 16);
            #pragma unroll
            for (int c = 0; c < 4; c++) {
                float4 v = eap[c];
                ea[4*c+0] = v.x; ea[4*c+1] = v.y; ea[4*c+2] = v.z; ea[4*c+3] = v.w;
            }
        } else {
            #pragma unroll
            for (int c = 0; c < 16; c++) ea[c] = 0.f;
        }
        int k0 = th * 32;
        #pragma unroll 4
        for (int k = k0; k < k0 + 32; k++) {
            float z = S->be1s[k];
            const float4* wp = (const float4*)S->we1t[k];
            #pragma unroll
            for (int q = 0; q < 4; q++) {
                float4 w = wp[q];
                z = fmaf(ea[4*q+0], w.x, z);
                z = fmaf(ea[4*q+1], w.y, z);
                z = fmaf(ea[4*q+2], w.z, z);
                z = fmaf(ea[4*q+3], w.w, z);
            }
            S->zs[k][el] = fmaxf(z, 0.f);
        }
    }
    __syncthreads();

    // ---- Phase B: 4 edges x 8 j per thread
    int eg = tid >> 3;          // 0..31
    int jg = tid & 7;           // 0..7  (contiguous lanes -> shfl reduce)
    int e0 = eg * 4;
    int j0 = jg * 8;

    u64 acc2[16];               // [edge i][j-pair p]
    #pragma unroll
    for (int i = 0; i < 4; i++) {
        int s = S->sidx[e0 + i];
        int t = S->tidx[e0 + i];
        const float4* ps = (const float4*)&g_hq[(size_t)s * H + j0];
        const float4* pt = (const float4*)&g_hq[(size_t)t * H + j0];
        float4 a0 = ps[0], a1 = ps[1], b0 = pt[0], b1 = pt[1];
        float4 c0 = *(const float4*)&S->b2os[j0];
        float4 c1 = *(const float4*)&S->b2os[j0 + 4];
        acc2[i*4+0] = pack2(a0.x + b0.x + c0.x, a0.y + b0.y + c0.y);
        acc2[i*4+1] = pack2(a0.z + b0.z + c0.z, a0.w + b0.w + c0.w);
        acc2[i*4+2] = pack2(a1.x + b1.x + c1.x, a1.y + b1.y + c1.y);
        acc2[i*4+3] = pack2(a1.z + b1.z + c1.z, a1.w + b1.w + c1.w);
    }

    #pragma unroll 2
    for (int k = 0; k < H; k++) {
        float4 zv = *(const float4*)&S->zs[k][e0];
        const u64* wp = (const u64*)&S->w2os[k][j0];
        u64 w0 = wp[0], w1 = wp[1], w2 = wp[2], w3 = wp[3];
        u64 z0 = pack2(zv.x, zv.x), z1 = pack2(zv.y, zv.y);
        u64 z2 = pack2(zv.z, zv.z), z3 = pack2(zv.w, zv.w);
        acc2[0]  = ffma2(z0, w0, acc2[0]);  acc2[1]  = ffma2(z0, w1, acc2[1]);
        acc2[2]  = ffma2(z0, w2, acc2[2]);  acc2[3]  = ffma2(z0, w3, acc2[3]);
        acc2[4]  = ffma2(z1, w0, acc2[4]);  acc2[5]  = ffma2(z1, w1, acc2[5]);
        acc2[6]  = ffma2(z1, w2, acc2[6]);  acc2[7]  = ffma2(z1, w3, acc2[7]);
        acc2[8]  = ffma2(z2, w0, acc2[8]);  acc2[9]  = ffma2(z2, w1, acc2[9]);
        acc2[10] = ffma2(z2, w2, acc2[10]); acc2[11] = ffma2(z2, w3, acc2[11]);
        acc2[12] = ffma2(z3, w0, acc2[12]); acc2[13] = ffma2(z3, w1, acc2[13]);
        acc2[14] = ffma2(z3, w2, acc2[14]); acc2[15] = ffma2(z3, w3, acc2[15]);
    }

    // epilogue: relu + dot(wo2 slice) + shuffle-reduce over 8 j-lanes
    float r[4];
    #pragma unroll
    for (int i = 0; i < 4; i++) {
        float po = 0.f;
        #pragma unroll
        for (int p = 0; p < 4; p++) {
            float2 a = unpack2(acc2[i*4+p]);
            po = fmaf(fmaxf(a.x, 0.f), S->wo2s[j0 + 2*p + 0], po);
            po = fmaf(fmaxf(a.y, 0.f), S->wo2s[j0 + 2*p + 1], po);
        }
        po += __shfl_xor_sync(0xffffffffu, po, 4);
        po += __shfl_xor_sync(0xffffffffu, po, 2);
        po += __shfl_xor_sync(0xffffffffu, po, 1);
        r[i] = po;
    }
    if (jg == 0) {
        float b = S->bo2s;
        #pragma unroll
        for (int i = 0; i < 4; i++)
            r[i] = 1.0f / (1.0f + expf(-(r[i] + b)));
        long long e = e_base + e0;
        if (e + 3 < E) {
            *(float4*)&out[e] = make_float4(r[0], r[1], r[2], r[3]);
        } else {
            #pragma unroll
            for (int i = 0; i < 4; i++)
                if (e + i < E) out[e + i] = r[i];
        }
    }
}

// ----------------------------------------------------------------------------
extern "C" void kernel_launch(void* const* d_in, const int* in_sizes, int n_in,
                              void* d_out, int out_size) {
    const float* x   = (const float*)d_in[0];
    const int*   ei  = (const int*)d_in[1];       // int32 (JAX x64 disabled)
    const float* eat = (const float*)d_in[2];
    const float* We1 = (const float*)d_in[3];
    const float* be1 = (const float*)d_in[4];
    const float* We2 = (const float*)d_in[5];
    const float* be2 = (const float*)d_in[6];
    const float* Wl0 = (const float*)d_in[7];
    const float* bl0 = (const float*)d_in[8];
    const float* Wr0 = (const float*)d_in[9];
    const float* Wl1 = (const float*)d_in[10];
    const float* bl1 = (const float*)d_in[11];
    const float* Wr1 = (const float*)d_in[12];
    const float* Wo1 = (const float*)d_in[13];
    const float* bo1 = (const float*)d_in[14];
    const float* Wo2 = (const float*)d_in[15];
    const float* bo2 = (const float*)d_in[16];

    int N = in_sizes[0] / FI;          // 100000
    if (N > NN) N = NN;
    int E = in_sizes[1] / 2;           // 1000000
    float* out = (float*)d_out;

    int nb = (N + 15) / 16;
    unsigned sth = (unsigned)E * 16u;
    unsigned sblocks = (sth + 255u) / 256u;
    int smem_edge = (int)sizeof(EdgeSmem);
    cudaFuncSetAttribute(k_edge, cudaFuncAttributeMaxDynamicSharedMemorySize, smem_edge);

    k_prep<<<1, H>>>(We2, Wo1, be2, bo1);
    k_node_lin128<<<nb, 256>>>(x, Wl0, nullptr, N, 0);   // g_xl; zero g_s/g_cnt
    k_node_lin128<<<nb, 256>>>(x, Wr0, bl0, N, 1);       // g_xb
    k_scatter<<<sblocks, 256>>>(ei, E, 1);               // layer-0 aggregation + counts
    k_node_mid<<<nb, 256>>>(Wl1, Wr1, bl1, N);           // h0 -> layer-1 projections
    k_scatter<<<sblocks, 256>>>(ei, E, 0);               // layer-1 aggregation
    k_node_fin<<<nb, 256>>>(Wo1, N);                     // h1 -> g_hq
    k_edge<<<(E + TE - 1) / TE, 256, smem_edge>>>(ei, E, eat, We1, be1, Wo2, bo2, out);
}

// round 8
// speedup vs baseline: 1.7512x; 1.4316x over previous
#include <cuda_runtime.h>
#include <cstdint>
#include <math.h>

#define NN 100000
#define FI 128
#define H  64
#define TE 128   // edges per block in k_edge

typedef unsigned long long u64;

__device__ __forceinline__ u64 ffma2(u64 a, u64 b, u64 c) {
    u64 d;
    asm("fma.rn.f32x2 %0, %1, %2, %3;" : "=l"(d) : "l"(a), "l"(b), "l"(c));
    return d;
}
__device__ __forceinline__ float2 unpack2(u64 p) {
    float2 f;
    asm("mov.b64 {%0,%1}, %2;" : "=f"(f.x), "=f"(f.y) : "l"(p));
    return f;
}
__device__ __forceinline__ u64 pack2(float lo, float hi) {
    u64 p;
    asm("mov.b64 %0, {%1,%2};" : "=l"(p) : "f"(lo), "f"(hi));
    return p;
}

// Scratch (device globals). 16B-aligned for float4 access.
__device__ __align__(16) float g_xl[(size_t)NN * H];
__device__ __align__(16) float g_xb[(size_t)NN * H];
__device__ __align__(16) float g_s [(size_t)NN * H];
__device__ __align__(16) float g_cnt[NN];
__device__ __align__(16) float g_hq[(size_t)NN * H];
__device__ __align__(16) float g_W2o[H * H];
__device__ __align__(16) float g_b2o[H];

// ---------------------------------------------------------------- prep (parallel)
__global__ void k_prep(const float* __restrict__ We2, const float* __restrict__ Wo1,
                       const float* __restrict__ be2, const float* __restrict__ bo1) {
    int j = threadIdx.x;
    int b = blockIdx.x;
    if (b < H) {
        float acc = 0.f;
        #pragma unroll 8
        for (int k = 0; k < H; k++) acc += We2[b * H + k] * Wo1[k * H + j];
        g_W2o[b * H + j] = acc;
    } else {
        float acc = bo1[j];
        #pragma unroll 8
        for (int k = 0; k < H; k++) acc += be2[k] * Wo1[k * H + j];
        g_b2o[j] = acc;
    }
}

// ------------------------------------------------- fused node linear: xl = x@Wl, xb = x@Wr + bl
// 64 nodes/block, 256 threads; thread = 4 nodes x 4 j; x staged transposed.
__global__ void __launch_bounds__(256) k_node_dual(const float* __restrict__ x,
                                                   const float* __restrict__ Wl,
                                                   const float* __restrict__ Wr,
                                                   const float* __restrict__ bl, int N) {
    extern __shared__ float sm[];
    float* xT = sm;                 // [128][64]  32KB
    float* wl = sm + FI * 64;       // [128][64]  32KB
    float* wr = wl + FI * H;        // [128][64]  32KB
    int tid = threadIdx.x;
    #pragma unroll
    for (int i = 0; i < 8; i++) {
        ((float4*)wl)[tid + i * 256] = ((const float4*)Wl)[tid + i * 256];
        ((float4*)wr)[tid + i * 256] = ((const float4*)Wr)[tid + i * 256];
    }
    int n_l = tid & 63, q = tid >> 6;
    int n = blockIdx.x * 64 + n_l;
    if (n < N) {
        #pragma unroll
        for (int r = 0; r < 8; r++) {
            int i0 = q * 32 + r * 4;
            float4 v = *(const float4*)&x[(size_t)n * FI + i0];
            xT[(i0 + 0) * 64 + n_l] = v.x;
            xT[(i0 + 1) * 64 + n_l] = v.y;
            xT[(i0 + 2) * 64 + n_l] = v.z;
            xT[(i0 + 3) * 64 + n_l] = v.w;
        }
    }
    __syncthreads();

    int ng = tid >> 4, jg = tid & 15, j0 = jg * 4;
    u64 al[8], ar[8];
    #pragma unroll
    for (int c = 0; c < 8; c++) { al[c] = 0; ar[c] = 0; }

    #pragma unroll 4
    for (int i = 0; i < FI; i++) {
        float4 xv = *(const float4*)&xT[i * 64 + ng * 4];
        const u64* pl = (const u64*)&wl[i * H + j0];
        const u64* pr = (const u64*)&wr[i * H + j0];
        u64 l0 = pl[0], l1 = pl[1], r0 = pr[0], r1 = pr[1];
        u64 x0 = pack2(xv.x, xv.x), x1 = pack2(xv.y, xv.y);
        u64 x2 = pack2(xv.z, xv.z), x3 = pack2(xv.w, xv.w);
        al[0] = ffma2(x0, l0, al[0]); al[1] = ffma2(x0, l1, al[1]);
        al[2] = ffma2(x1, l0, al[2]); al[3] = ffma2(x1, l1, al[3]);
        al[4] = ffma2(x2, l0, al[4]); al[5] = ffma2(x2, l1, al[5]);
        al[6] = ffma2(x3, l0, al[6]); al[7] = ffma2(x3, l1, al[7]);
        ar[0] = ffma2(x0, r0, ar[0]); ar[1] = ffma2(x0, r1, ar[1]);
        ar[2] = ffma2(x1, r0, ar[2]); ar[3] = ffma2(x1, r1, ar[3]);
        ar[4] = ffma2(x2, r0, ar[4]); ar[5] = ffma2(x2, r1, ar[5]);
        ar[6] = ffma2(x3, r0, ar[6]); ar[7] = ffma2(x3, r1, ar[7]);
    }

    float4 bb = *(const float4*)&bl[j0];
    int nb0 = blockIdx.x * 64 + ng * 4;
    #pragma unroll
    for (int c = 0; c < 4; c++) {
        int n2 = nb0 + c;
        if (n2 < N) {
            size_t o = (size_t)n2 * H + j0;
            float2 lo = unpack2(al[c * 2]), hi = unpack2(al[c * 2 + 1]);
            *(float4*)&g_xl[o] = make_float4(lo.x, lo.y, hi.x, hi.y);
            float2 ro = unpack2(ar[c * 2]), rh = unpack2(ar[c * 2 + 1]);
            *(float4*)&g_xb[o] = make_float4(ro.x + bb.x, ro.y + bb.y, rh.x + bb.z, rh.y + bb.w);
            *(float4*)&g_s[o] = make_float4(0.f, 0.f, 0.f, 0.f);
            if (jg == 0) g_cnt[n2] = 0.f;
        }
    }
}

// ------------------------------------------------- edge scatter
__global__ void k_scatter(const int* __restrict__ ei, int E, int do_cnt) {
    unsigned idx = blockIdx.x * 256u + threadIdx.x;
    unsigned e = idx >> 4;
    if (e >= (unsigned)E) return;
    int k4 = (int)(idx & 15u) * 4;
    int s = ei[e];
    int t = ei[(size_t)E + e];
    float4 v = *(const float4*)(g_xl + (size_t)s * H + k4);
    float* p = g_s + (size_t)t * H + k4;
    asm volatile("red.global.add.v4.f32 [%0], {%1,%2,%3,%4};"
                 :: "l"(p), "f"(v.x), "f"(v.y), "f"(v.z), "f"(v.w) : "memory");
    if (do_cnt && k4 == 0) atomicAdd(g_cnt + t, 1.0f);
}

// ------------------------------------------------- h0 = relu(s/cnt + xb); dual project Wl1/Wr1
__global__ void __launch_bounds__(256) k_node_mid(const float* __restrict__ Wl,
                                                  const float* __restrict__ Wr,
                                                  const float* __restrict__ bl, int N) {
    extern __shared__ float sm[];
    float* hT = sm;                 // [64][64] 16KB
    float* wl = sm + H * 64;        // 16KB
    float* wr = wl + H * H;         // 16KB
    int tid = threadIdx.x;
    #pragma unroll
    for (int i = 0; i < 4; i++) {
        ((float4*)wl)[tid + i * 256] = ((const float4*)Wl)[tid + i * 256];
        ((float4*)wr)[tid + i * 256] = ((const float4*)Wr)[tid + i * 256];
    }
    {
        int n_l = tid >> 2, part = tid & 3, jp = part * 16;
        int n = blockIdx.x * 64 + n_l;
        if (n < N) {
            float inv = 1.0f / fmaxf(g_cnt[n], 1.0f);
            size_t o = (size_t)n * H + jp;
            #pragma unroll
            for (int c = 0; c < 4; c++) {
                float4 s4 = *(const float4*)&g_s[o + c * 4];
                float4 b4 = *(const float4*)&g_xb[o + c * 4];
                int jb = jp + c * 4;
                hT[(jb + 0) * 64 + n_l] = fmaxf(fmaf(s4.x, inv, b4.x), 0.f);
                hT[(jb + 1) * 64 + n_l] = fmaxf(fmaf(s4.y, inv, b4.y), 0.f);
                hT[(jb + 2) * 64 + n_l] = fmaxf(fmaf(s4.z, inv, b4.z), 0.f);
                hT[(jb + 3) * 64 + n_l] = fmaxf(fmaf(s4.w, inv, b4.w), 0.f);
                *(float4*)&g_s[o + c * 4] = make_float4(0.f, 0.f, 0.f, 0.f);
            }
        } else {
            #pragma unroll
            for (int c = 0; c < 16; c++) hT[(jp + c) * 64 + n_l] = 0.f;
        }
    }
    __syncthreads();

    int ng = tid >> 4, jg = tid & 15, j0 = jg * 4;
    u64 al[8], ar[8];
    #pragma unroll
    for (int c = 0; c < 8; c++) { al[c] = 0; ar[c] = 0; }

    #pragma unroll 4
    for (int k = 0; k < H; k++) {
        float4 xv = *(const float4*)&hT[k * 64 + ng * 4];
        const u64* pl = (const u64*)&wl[k * H + j0];
        const u64* pr = (const u64*)&wr[k * H + j0];
        u64 l0 = pl[0], l1 = pl[1], r0 = pr[0], r1 = pr[1];
        u64 x0 = pack2(xv.x, xv.x), x1 = pack2(xv.y, xv.y);
        u64 x2 = pack2(xv.z, xv.z), x3 = pack2(xv.w, xv.w);
        al[0] = ffma2(x0, l0, al[0]); al[1] = ffma2(x0, l1, al[1]);
        al[2] = ffma2(x1, l0, al[2]); al[3] = ffma2(x1, l1, al[3]);
        al[4] = ffma2(x2, l0, al[4]); al[5] = ffma2(x2, l1, al[5]);
        al[6] = ffma2(x3, l0, al[6]); al[7] = ffma2(x3, l1, al[7]);
        ar[0] = ffma2(x0, r0, ar[0]); ar[1] = ffma2(x0, r1, ar[1]);
        ar[2] = ffma2(x1, r0, ar[2]); ar[3] = ffma2(x1, r1, ar[3]);
        ar[4] = ffma2(x2, r0, ar[4]); ar[5] = ffma2(x2, r1, ar[5]);
        ar[6] = ffma2(x3, r0, ar[6]); ar[7] = ffma2(x3, r1, ar[7]);
    }

    float4 bb = *(const float4*)&bl[j0];
    int nb0 = blockIdx.x * 64 + ng * 4;
    #pragma unroll
    for (int c = 0; c < 4; c++) {
        int n2 = nb0 + c;
        if (n2 < N) {
            size_t o = (size_t)n2 * H + j0;
            float2 lo = unpack2(al[c * 2]), hi = unpack2(al[c * 2 + 1]);
            *(float4*)&g_xl[o] = make_float4(lo.x, lo.y, hi.x, hi.y);
            float2 ro = unpack2(ar[c * 2]), rh = unpack2(ar[c * 2 + 1]);
            *(float4*)&g_xb[o] = make_float4(ro.x + bb.x, ro.y + bb.y, rh.x + bb.z, rh.y + bb.w);
        }
    }
}

// ------------------------------------------------- h1 = relu(s/cnt + xb); g_hq = h1 @ Wo1
__global__ void __launch_bounds__(256) k_node_fin(const float* __restrict__ Wo1, int N) {
    __shared__ float hT[H * 64];    // 16KB
    __shared__ float ws[H * H];     // 16KB
    int tid = threadIdx.x;
    #pragma unroll
    for (int i = 0; i < 4; i++)
        ((float4*)ws)[tid + i * 256] = ((const float4*)Wo1)[tid + i * 256];
    {
        int n_l = tid >> 2, part = tid & 3, jp = part * 16;
        int n = blockIdx.x * 64 + n_l;
        if (n < N) {
            float inv = 1.0f / fmaxf(g_cnt[n], 1.0f);
            size_t o = (size_t)n * H + jp;
            #pragma unroll
            for (int c = 0; c < 4; c++) {
                float4 s4 = *(const float4*)&g_s[o + c * 4];
                float4 b4 = *(const float4*)&g_xb[o + c * 4];
                int jb = jp + c * 4;
                hT[(jb + 0) * 64 + n_l] = fmaxf(fmaf(s4.x, inv, b4.x), 0.f);
                hT[(jb + 1) * 64 + n_l] = fmaxf(fmaf(s4.y, inv, b4.y), 0.f);
                hT[(jb + 2) * 64 + n_l] = fmaxf(fmaf(s4.z, inv, b4.z), 0.f);
                hT[(jb + 3) * 64 + n_l] = fmaxf(fmaf(s4.w, inv, b4.w), 0.f);
            }
        } else {
            #pragma unroll
            for (int c = 0; c < 16; c++) hT[(jp + c) * 64 + n_l] = 0.f;
        }
    }
    __syncthreads();

    int ng = tid >> 4, jg = tid & 15, j0 = jg * 4;
    u64 ac[8];
    #pragma unroll
    for (int c = 0; c < 8; c++) ac[c] = 0;

    #pragma unroll 4
    for (int k = 0; k < H; k++) {
        float4 xv = *(const float4*)&hT[k * 64 + ng * 4];
        const u64* pw = (const u64*)&ws[k * H + j0];
        u64 w0 = pw[0], w1 = pw[1];
        u64 x0 = pack2(xv.x, xv.x), x1 = pack2(xv.y, xv.y);
        u64 x2 = pack2(xv.z, xv.z), x3 = pack2(xv.w, xv.w);
        ac[0] = ffma2(x0, w0, ac[0]); ac[1] = ffma2(x0, w1, ac[1]);
        ac[2] = ffma2(x1, w0, ac[2]); ac[3] = ffma2(x1, w1, ac[3]);
        ac[4] = ffma2(x2, w0, ac[4]); ac[5] = ffma2(x2, w1, ac[5]);
        ac[6] = ffma2(x3, w0, ac[6]); ac[7] = ffma2(x3, w1, ac[7]);
    }

    int nb0 = blockIdx.x * 64 + ng * 4;
    #pragma unroll
    for (int c = 0; c < 4; c++) {
        int n2 = nb0 + c;
        if (n2 < N) {
            float2 lo = unpack2(ac[c * 2]), hi = unpack2(ac[c * 2 + 1]);
            *(float4*)&g_hq[(size_t)n2 * H + j0] = make_float4(lo.x, lo.y, hi.x, hi.y);
        }
    }
}

// ------------------------------------------------- per-edge head: block-tiled GEMM (unchanged)
struct __align__(16) EdgeSmem {
    float zs[H][TE];
    float w2os[H][H];
    float we1t[H][16];
    float be1s[H];
    float b2os[H];
    float wo2s[H];
    int   sidx[TE];
    int   tidx[TE];
    float bo2s;
};

__global__ void __launch_bounds__(256) k_edge(const int* __restrict__ ei, int E,
                                              const float* __restrict__ edge_attr,
                                              const float* __restrict__ We1,
                                              const float* __restrict__ be1,
                                              const float* __restrict__ Wo2,
                                              const float* __restrict__ bo2,
                                              float* __restrict__ out) {
    extern __shared__ char smem_raw[];
    EdgeSmem* S = (EdgeSmem*)smem_raw;
    int tid = threadIdx.x;
    long long e_base = (long long)blockIdx.x * TE;

    #pragma unroll
    for (int i = 0; i < (H * H / 4) / 256; i++)
        ((float4*)S->w2os)[tid + i * 256] = ((const float4*)g_W2o)[tid + i * 256];
    #pragma unroll
    for (int r = 0; r < 4; r++) {
        int idx = tid + r * 256;
        int kk = idx >> 4, ii = idx & 15;
        S->we1t[kk][ii] = We1[ii * H + kk];
    }
    if (tid < H) {
        S->be1s[tid] = be1[tid];
        S->b2os[tid] = g_b2o[tid];
        S->wo2s[tid] = Wo2[tid];
    }
    if (tid == 0) S->bo2s = bo2[0];
    if (tid < TE) {
        long long e = e_base + tid;
        S->sidx[tid] = (e < E) ? ei[e] : 0;
    } else {
        int el = tid - TE;
        long long e = e_base + el;
        S->tidx[el] = (e < E) ? ei[(size_t)E + e] : 0;
    }
    __syncthreads();

    {
        int th = tid >> 7;
        int el = tid & (TE - 1);
        long long e = e_base + el;
        float ea[16];
        if (e < E) {
            const float4* eap = (const float4*)(edge_attr + (size_t)e * 16);
            #pragma unroll
            for (int c = 0; c < 4; c++) {
                float4 v = eap[c];
                ea[4*c+0] = v.x; ea[4*c+1] = v.y; ea[4*c+2] = v.z; ea[4*c+3] = v.w;
            }
        } else {
            #pragma unroll
            for (int c = 0; c < 16; c++) ea[c] = 0.f;
        }
        int k0 = th * 32;
        #pragma unroll 4
        for (int k = k0; k < k0 + 32; k++) {
            float z = S->be1s[k];
            const float4* wp = (const float4*)S->we1t[k];
            #pragma unroll
            for (int q = 0; q < 4; q++) {
                float4 w = wp[q];
                z = fmaf(ea[4*q+0], w.x, z);
                z = fmaf(ea[4*q+1], w.y, z);
                z = fmaf(ea[4*q+2], w.z, z);
                z = fmaf(ea[4*q+3], w.w, z);
            }
            S->zs[k][el] = fmaxf(z, 0.f);
        }
    }
    __syncthreads();

    int eg = tid >> 3;
    int jg = tid & 7;
    int e0 = eg * 4;
    int j0 = jg * 8;

    u64 acc2[16];
    #pragma unroll
    for (int i = 0; i < 4; i++) {
        int s = S->sidx[e0 + i];
        int t = S->tidx[e0 + i];
        const float4* ps = (const float4*)&g_hq[(size_t)s * H + j0];
        const float4* pt = (const float4*)&g_hq[(size_t)t * H + j0];
        float4 a0 = ps[0], a1 = ps[1], b0 = pt[0], b1 = pt[1];
        float4 c0 = *(const float4*)&S->b2os[j0];
        float4 c1 = *(const float4*)&S->b2os[j0 + 4];
        acc2[i*4+0] = pack2(a0.x + b0.x + c0.x, a0.y + b0.y + c0.y);
        acc2[i*4+1] = pack2(a0.z + b0.z + c0.z, a0.w + b0.w + c0.w);
        acc2[i*4+2] = pack2(a1.x + b1.x + c1.x, a1.y + b1.y + c1.y);
        acc2[i*4+3] = pack2(a1.z + b1.z + c1.z, a1.w + b1.w + c1.w);
    }

    #pragma unroll 2
    for (int k = 0; k < H; k++) {
        float4 zv = *(const float4*)&S->zs[k][e0];
        const u64* wp = (const u64*)&S->w2os[k][j0];
        u64 w0 = wp[0], w1 = wp[1], w2 = wp[2], w3 = wp[3];
        u64 z0 = pack2(zv.x, zv.x), z1 = pack2(zv.y, zv.y);
        u64 z2 = pack2(zv.z, zv.z), z3 = pack2(zv.w, zv.w);
        acc2[0]  = ffma2(z0, w0, acc2[0]);  acc2[1]  = ffma2(z0, w1, acc2[1]);
        acc2[2]  = ffma2(z0, w2, acc2[2]);  acc2[3]  = ffma2(z0, w3, acc2[3]);
        acc2[4]  = ffma2(z1, w0, acc2[4]);  acc2[5]  = ffma2(z1, w1, acc2[5]);
        acc2[6]  = ffma2(z1, w2, acc2[6]);  acc2[7]  = ffma2(z1, w3, acc2[7]);
        acc2[8]  = ffma2(z2, w0, acc2[8]);  acc2[9]  = ffma2(z2, w1, acc2[9]);
        acc2[10] = ffma2(z2, w2, acc2[10]); acc2[11] = ffma2(z2, w3, acc2[11]);
        acc2[12] = ffma2(z3, w0, acc2[12]); acc2[13] = ffma2(z3, w1, acc2[13]);
        acc2[14] = ffma2(z3, w2, acc2[14]); acc2[15] = ffma2(z3, w3, acc2[15]);
    }

    float r[4];
    #pragma unroll
    for (int i = 0; i < 4; i++) {
        float po = 0.f;
        #pragma unroll
        for (int p = 0; p < 4; p++) {
            float2 a = unpack2(acc2[i*4+p]);
            po = fmaf(fmaxf(a.x, 0.f), S->wo2s[j0 + 2*p + 0], po);
            po = fmaf(fmaxf(a.y, 0.f), S->wo2s[j0 + 2*p + 1], po);
        }
        po += __shfl_xor_sync(0xffffffffu, po, 4);
        po += __shfl_xor_sync(0xffffffffu, po, 2);
        po += __shfl_xor_sync(0xffffffffu, po, 1);
        r[i] = po;
    }
    if (jg == 0) {
        float b = S->bo2s;
        #pragma unroll
        for (int i = 0; i < 4; i++)
            r[i] = 1.0f / (1.0f + expf(-(r[i] + b)));
        long long e = e_base + e0;
        if (e + 3 < E) {
            *(float4*)&out[e] = make_float4(r[0], r[1], r[2], r[3]);
        } else {
            #pragma unroll
            for (int i = 0; i < 4; i++)
                if (e + i < E) out[e + i] = r[i];
        }
    }
}

// ----------------------------------------------------------------------------
extern "C" void kernel_launch(void* const* d_in, const int* in_sizes, int n_in,
                              void* d_out, int out_size) {
    const float* x   = (const float*)d_in[0];
    const int*   ei  = (const int*)d_in[1];       // int32 (JAX x64 disabled)
    const float* eat = (const float*)d_in[2];
    const float* We1 = (const float*)d_in[3];
    const float* be1 = (const float*)d_in[4];
    const float* We2 = (const float*)d_in[5];
    const float* be2 = (const float*)d_in[6];
    const float* Wl0 = (const float*)d_in[7];
    const float* bl0 = (const float*)d_in[8];
    const float* Wr0 = (const float*)d_in[9];
    const float* Wl1 = (const float*)d_in[10];
    const float* bl1 = (const float*)d_in[11];
    const float* Wr1 = (const float*)d_in[12];
    const float* Wo1 = (const float*)d_in[13];
    const float* bo1 = (const float*)d_in[14];
    const float* Wo2 = (const float*)d_in[15];
    const float* bo2 = (const float*)d_in[16];

    int N = in_sizes[0] / FI;          // 100000
    if (N > NN) N = NN;
    int E = in_sizes[1] / 2;           // 1000000
    float* out = (float*)d_out;

    int nb64 = (N + 63) / 64;
    unsigned sth = (unsigned)E * 16u;
    unsigned sblocks = (sth + 255u) / 256u;

    int smem_dual = (FI * 64 + FI * H + FI * H) * 4;   // 96KB
    int smem_mid  = (H * 64 + H * H + H * H) * 4;      // 48KB
    int smem_edge = (int)sizeof(EdgeSmem);
    cudaFuncSetAttribute(k_node_dual, cudaFuncAttributeMaxDynamicSharedMemorySize, smem_dual);
    cudaFuncSetAttribute(k_node_mid,  cudaFuncAttributeMaxDynamicSharedMemorySize, smem_mid);
    cudaFuncSetAttribute(k_edge,      cudaFuncAttributeMaxDynamicSharedMemorySize, smem_edge);

    k_prep<<<H + 1, H>>>(We2, Wo1, be2, bo1);
    k_node_dual<<<nb64, 256, smem_dual>>>(x, Wl0, Wr0, bl0, N);
    k_scatter<<<sblocks, 256>>>(ei, E, 1);
    k_node_mid<<<nb64, 256, smem_mid>>>(Wl1, Wr1, bl1, N);
    k_scatter<<<sblocks, 256>>>(ei, E, 0);
    k_node_fin<<<nb64, 256>>>(Wo1, N);
    k_edge<<<(E + TE - 1) / TE, 256, smem_edge>>>(ei, E, eat, We1, be1, Wo2, bo2, out);
}